// round 12
// baseline (speedup 1.0000x reference)
#include <cuda_runtime.h>
#include <cuda_fp16.h>

// Problem constants
#define BATCH 32
#define CIN   256
#define COUT  256
#define NEXP  8
#define CHID  64
#define HW    3136   // 56*56

// GEMM tiling: CTA 64 x 112, 4 warps (2m x 2n), warp tile 32 x 56
#define BM 64
#define BK 32             // 2 k-steps of 16
#define NCHUNKS (CIN / BK)
#define NSTAGES 3

// per-stage smem: A private per warp 4*2048=8192; B halves 2*32*144=9216
#define A_BYTES 8192
#define STG_BYTES 17408
#define SM_BYTES (NSTAGES * STG_BYTES)   // 52224

// Device scratch (allocation-free per harness rules)
__device__ float g_pooled[BATCH * CIN];
__device__ float g_attn[BATCH * NEXP];
// A (w_dyn) fp16 in m16n8k16 A-fragment layout: [b][mt 16][kstep 16][lane 32][8 halves]
__device__ __half g_wh[BATCH * 16 * 16 * 32 * 8];        // 4 MB
// fp16 copy of x
__device__ __half g_xh[(size_t)BATCH * CIN * HW];        // 52 MB

__device__ __forceinline__ unsigned smem_u32(const void* p) {
    unsigned a;
    asm("{ .reg .u64 t; cvta.to.shared.u64 t, %1; cvt.u32.u64 %0, t; }" : "=r"(a) : "l"(p));
    return a;
}
__device__ __forceinline__ void cp_async16(unsigned dst, const void* src) {
    asm volatile("cp.async.cg.shared.global [%0], [%1], 16;" :: "r"(dst), "l"(src) : "memory");
}
__device__ __forceinline__ void cp_async16ca(unsigned dst, const void* src) {
    asm volatile("cp.async.ca.shared.global [%0], [%1], 16;" :: "r"(dst), "l"(src) : "memory");
}
#define CP_COMMIT() asm volatile("cp.async.commit_group;" ::: "memory")
#define CP_WAIT2()  asm volatile("cp.async.wait_group 2;" ::: "memory")
#define CP_WAIT1()  asm volatile("cp.async.wait_group 1;" ::: "memory")
#define CP_WAIT0()  asm volatile("cp.async.wait_group 0;" ::: "memory")
#define PAIR_BAR(id) asm volatile("bar.sync %0, 64;" :: "r"(id) : "memory")

__device__ __forceinline__ void lds128(unsigned* r, unsigned addr) {
    asm volatile("ld.shared.v4.b32 {%0,%1,%2,%3}, [%4];"
                 : "=r"(r[0]), "=r"(r[1]), "=r"(r[2]), "=r"(r[3]) : "r"(addr));
}
__device__ __forceinline__ void ldmx2t(unsigned& b0, unsigned& b1, unsigned addr) {
    asm volatile("ldmatrix.sync.aligned.m8n8.x2.trans.shared.b16 {%0,%1}, [%2];"
                 : "=r"(b0), "=r"(b1) : "r"(addr));
}
__device__ __forceinline__ void mma16(float4& d, const unsigned* a, unsigned b0, unsigned b1) {
    asm volatile(
        "mma.sync.aligned.m16n8k16.row.col.f32.f16.f16.f32 "
        "{%0,%1,%2,%3}, {%4,%5,%6,%7}, {%8,%9}, {%0,%1,%2,%3};"
        : "+f"(d.x), "+f"(d.y), "+f"(d.z), "+f"(d.w)
        : "r"(a[0]), "r"(a[1]), "r"(a[2]), "r"(a[3]), "r"(b0), "r"(b1));
}

// ---------------------------------------------------------------------------
// Kernel 1: global average pool + fp16 copy of x
// ---------------------------------------------------------------------------
__global__ void pool_kernel(const float* __restrict__ x) {
    const int bc = blockIdx.x;
    const float* __restrict__ p = x + (size_t)bc * HW;
    __half2* __restrict__ q2 = (__half2*)(g_xh + (size_t)bc * HW);
    const int tid = threadIdx.x;

    float s = 0.0f;
    const float4* p4 = (const float4*)p;
    for (int i = tid; i < HW / 4; i += 256) {
        float4 v = p4[i];
        s += v.x + v.y + v.z + v.w;
        __half2 h2[2];
        h2[0] = __floats2half2_rn(v.x, v.y);
        h2[1] = __floats2half2_rn(v.z, v.w);
        *(uint2*)(q2 + i * 2) = *(uint2*)h2;
    }
    for (int off = 16; off > 0; off >>= 1)
        s += __shfl_xor_sync(0xFFFFFFFFu, s, off);

    __shared__ float red[8];
    if ((tid & 31) == 0) red[tid >> 5] = s;
    __syncthreads();
    if (tid == 0) {
        float t = 0.0f;
        #pragma unroll
        for (int w = 0; w < 8; w++) t += red[w];
        g_pooled[bc] = t * (1.0f / (float)HW);
    }
}

// ---------------------------------------------------------------------------
// Kernel 2: MLP + softmax -> attn (256 threads, 4-way split dot)
// ---------------------------------------------------------------------------
__global__ void attn_kernel(const float* __restrict__ w1,
                            const float* __restrict__ b1,
                            const float* __restrict__ w2,
                            const float* __restrict__ b2) {
    const int b = blockIdx.x;
    const int t = threadIdx.x;                 // 256

    __shared__ float sp[CIN];
    __shared__ float sh[CHID];
    __shared__ float sl[NEXP];

    sp[t] = g_pooled[b * CIN + t];
    __syncthreads();

    {
        const int o = t >> 2, q = t & 3;
        float p = 0.0f;
        const float* w1r = w1 + o * CIN + q * 64;
        const float* spq = sp + q * 64;
        #pragma unroll 16
        for (int j = 0; j < 64; j++) p = fmaf(w1r[j], spq[j], p);
        p += __shfl_xor_sync(0xFFFFFFFFu, p, 1);
        p += __shfl_xor_sync(0xFFFFFFFFu, p, 2);
        if (q == 0) sh[o] = fmaxf(p + b1[o], 0.0f);
    }
    __syncthreads();

    if (t < NEXP) {
        float l = b2[t];
        const float* w2r = w2 + t * CHID;
        #pragma unroll
        for (int j = 0; j < CHID; j++) l = fmaf(w2r[j], sh[j], l);
        sl[t] = l;
    }
    __syncthreads();

    if (t == 0) {
        float m = sl[0];
        #pragma unroll
        for (int e = 1; e < NEXP; e++) m = fmaxf(m, sl[e]);
        float sum = 0.0f;
        float ex[NEXP];
        #pragma unroll
        for (int e = 0; e < NEXP; e++) { ex[e] = __expf(sl[e] - m); sum += ex[e]; }
        float inv = 1.0f / sum;
        #pragma unroll
        for (int e = 0; e < NEXP; e++) g_attn[b * NEXP + e] = ex[e] * inv;
    }
}

// ---------------------------------------------------------------------------
// Kernel 3: w_dyn = attn . weights -> fp16 fragment layout, coalesced STG.128.
// ---------------------------------------------------------------------------
__global__ __launch_bounds__(512)
void wdyn_kernel(const float* __restrict__ weights) {
    const int mt = blockIdx.x;
    const int b0 = blockIdx.y * 4;
    const int t  = threadIdx.x;
    const int kstep = t >> 5;
    const int lane  = t & 31;

    __shared__ float sa[BATCH][NEXP];
    if (t < BATCH * NEXP) ((float*)sa)[t] = g_attn[t];
    __syncthreads();

    float w[8][NEXP];
    #pragma unroll
    for (int hp = 0; hp < 4; hp++) {
        const int r8 = hp & 1;
        const int k8 = hp >> 1;
        const int co = mt * 16 + r8 * 8 + (lane >> 2);
        const int ci = kstep * 16 + k8 * 8 + (lane & 3) * 2;
        #pragma unroll
        for (int e = 0; e < NEXP; e++) {
            const float2 v = *(const float2*)(weights + ((size_t)e * COUT + co) * CIN + ci);
            w[2 * hp][e] = v.x;
            w[2 * hp + 1][e] = v.y;
        }
    }

    #pragma unroll
    for (int bb = 0; bb < 4; bb++) {
        const int b = b0 + bb;
        float av[NEXP];
        #pragma unroll
        for (int e = 0; e < NEXP; e++) av[e] = sa[b][e];
        __half2 h2[4];
        #pragma unroll
        for (int hp = 0; hp < 4; hp++) {
            float s0 = 0.0f, s1 = 0.0f;
            #pragma unroll
            for (int e = 0; e < NEXP; e++) {
                s0 = fmaf(av[e], w[2 * hp][e], s0);
                s1 = fmaf(av[e], w[2 * hp + 1][e], s1);
            }
            h2[hp] = __floats2half2_rn(s0, s1);
        }
        const size_t unit = (((size_t)b * 16 + mt) * 16 + kstep) * 32 + lane;
        *(uint4*)(g_wh + unit * 8) = *(uint4*)h2;
    }
}

// ---------------------------------------------------------------------------
// Kernel 4: fp16 m16n8k16 batched GEMM, pair-scoped sync (NO __syncthreads)
//   CTA 64 x 112; 4 warps (2m x 2n); warp tile 32 x 56.
//   Each warp cp.asyncs its PRIVATE A slice (.ca, L1-cached dedup) and
//   half of its wn-pair's shared B half. Sync = 64-thread named barrier.
//   3-stage ring; per-warp wait_group covers own copies, barrier covers pair.
// ---------------------------------------------------------------------------
__global__ __launch_bounds__(128, 4)
void gemm_mma(float* __restrict__ out) {
    extern __shared__ char smc[];
    const unsigned sbase = smem_u32(smc);

    const int tid  = threadIdx.x;
    const int wid  = tid >> 5;
    const int lane = tid & 31;
    const int wm = wid >> 1;          // 0..1  (m offset 32*wm)
    const int wn = wid & 1;           // 0..1  (n offset 56*wn)

    const int n0 = blockIdx.x * 112;
    const int mb = blockIdx.y;        // 0..3
    const int b  = blockIdx.z;

    const __half* __restrict__ Afrag = g_wh + (size_t)(b * 16 + mb * 4) * (16 * 32 * 8);
    const __half* __restrict__ Bsrc = g_xh + (size_t)b * CIN * HW + n0 + wn * 56;

    float4 acc[2][7];
    #pragma unroll
    for (int i = 0; i < 2; i++)
        #pragma unroll
        for (int j = 0; j < 7; j++)
            acc[i][j] = make_float4(0.f, 0.f, 0.f, 0.f);

    // issue chunk c into stage s (per-warp private A + this warp's B share)
    auto issue = [&](int c, int s) {
        const unsigned stg = sbase + (unsigned)(s * STG_BYTES);
        const unsigned aw  = stg + (unsigned)(wid * 2048);
        const unsigned bh  = stg + A_BYTES + (unsigned)(wn * 4608);
        // A: 128 16B units for this warp (2 mtiles x 2 ks x 32 lanes), 4/lane
        #pragma unroll
        for (int i = 0; i < 4; i++) {
            const int u = lane * 4 + i;
            const int mtl = u >> 6, ks = (u >> 5) & 1, l = u & 31;
            cp_async16ca(aw + (unsigned)u * 16,
                         Afrag + ((size_t)((wm * 2 + mtl) * 16 + 2 * c + ks) * 32 + l) * 8);
        }
        // B half (32 rows x 56 cols): 224 units, split by wm (112 each)
        const int k0 = c * BK;
        #pragma unroll
        for (int i = 0; i < 3; i++) {
            const int u = wm * 112 + i * 32 + lane;
            const int row = u / 7, col = u % 7;
            cp_async16(bh + (unsigned)(row * 144 + col * 16),
                       Bsrc + (size_t)(k0 + row) * HW + col * 8);
        }
        if (lane < 16) {
            const int u = wm * 112 + 96 + lane;
            const int row = u / 7, col = u % 7;
            cp_async16(bh + (unsigned)(row * 144 + col * 16),
                       Bsrc + (size_t)(k0 + row) * HW + col * 8);
        }
    };

    // ---- prologue: 3 stages in flight ----
    issue(0, 0); CP_COMMIT();
    issue(1, 1); CP_COMMIT();
    issue(2, 2); CP_COMMIT();

    const unsigned aBase0 = (unsigned)(wid * 2048);
    const unsigned bBase0 = A_BYTES + (unsigned)(wn * 4608) + (unsigned)((lane & 15) * 144);
    const int barid = wn + 1;

    for (int c = 0; c < NCHUNKS; c++) {
        if (c <= NCHUNKS - 3) CP_WAIT2();
        else if (c == NCHUNKS - 2) CP_WAIT1();
        else CP_WAIT0();
        PAIR_BAR(barid);                       // pair's chunk-c data visible

        const unsigned stg = sbase + (unsigned)((c % NSTAGES) * STG_BYTES);
        const unsigned aS = stg + aBase0;
        const unsigned bS = stg + bBase0;

        #pragma unroll
        for (int ks = 0; ks < 2; ks++) {
            unsigned a0[4], a1[4];
            lds128(a0, aS + (unsigned)(((0 * 2 + ks) * 32 + lane) * 16));
            lds128(a1, aS + (unsigned)(((1 * 2 + ks) * 32 + lane) * 16));
            const unsigned bk = bS + (unsigned)(ks * 2304);
            #pragma unroll
            for (int nt = 0; nt < 7; nt++) {
                unsigned b0, b1;
                ldmx2t(b0, b1, bk + (unsigned)(nt * 16));
                mma16(acc[0][nt], a0, b0, b1);
                mma16(acc[1][nt], a1, b0, b1);
            }
        }

        if (c + 3 < NCHUNKS) {
            PAIR_BAR(barid);                   // pair done reading stage c%3
            issue(c + 3, c % NSTAGES);
            CP_COMMIT();
        }
    }

    // ---- epilogue ----
    const int rr = lane >> 2;
    const int t2 = (lane & 3) * 2;
    float* __restrict__ C = out + (size_t)b * COUT * HW
                          + (size_t)(mb * BM + wm * 32) * HW + n0 + wn * 56;
    #pragma unroll
    for (int it = 0; it < 2; it++)
        #pragma unroll
        for (int nt = 0; nt < 7; nt++) {
            float* p0 = C + (size_t)(it * 16 + rr) * HW + nt * 8 + t2;
            __stcs((float2*)p0, make_float2(acc[it][nt].x, acc[it][nt].y));
            __stcs((float2*)(p0 + 8 * HW), make_float2(acc[it][nt].z, acc[it][nt].w));
        }
}

// ---------------------------------------------------------------------------
// Launch
// ---------------------------------------------------------------------------
extern "C" void kernel_launch(void* const* d_in, const int* in_sizes, int n_in,
                              void* d_out, int out_size) {
    const float* x       = (const float*)d_in[0];
    const float* weights = (const float*)d_in[1];
    const float* w1      = (const float*)d_in[2];
    const float* b1      = (const float*)d_in[3];
    const float* w2      = (const float*)d_in[4];
    const float* b2      = (const float*)d_in[5];
    float* out = (float*)d_out;

    pool_kernel<<<BATCH * CIN, 256>>>(x);
    attn_kernel<<<BATCH, 256>>>(w1, b1, w2, b2);
    wdyn_kernel<<<dim3(16, 8), 512>>>(weights);

    cudaFuncSetAttribute(gemm_mma, cudaFuncAttributeMaxDynamicSharedMemorySize, SM_BYTES);
    dim3 grid(HW / 112, COUT / BM, BATCH);   // 28 x 4 x 32
    gemm_mma<<<grid, 128, SM_BYTES>>>(out);
}

// round 14
// speedup vs baseline: 1.1555x; 1.1555x over previous
#include <cuda_runtime.h>
#include <cuda_fp16.h>

// Problem constants
#define BATCH 32
#define CIN   256
#define COUT  256
#define NEXP  8
#define CHID  64
#define HW    3136   // 56*56

// GEMM tiling: tile 64 x 112 per CTA-step, 4 warps (2m x 2n), warp tile 32 x 56
#define BM 64
#define BK 32             // 2 k-steps of 16
#define NCHPT 8           // chunks per tile (CIN/BK)
#define NTILES 3584       // 28 n * 4 mb * 32 b
#define NSTAGES 4

// per-stage smem bytes: A = 4 mt * 2 ks * 32 lane * 16B = 4096; B = 32 * 240 = 7680
#define A_BYTES 4096
#define STG_BYTES 11776
#define SM_BYTES (NSTAGES * STG_BYTES)   // 47104

// Device scratch (allocation-free per harness rules)
__device__ float g_pooled[BATCH * CIN];
__device__ float g_attn[BATCH * NEXP];
// A (w_dyn) fp16 in m16n8k16 A-fragment layout: [b][mt 16][kstep 16][lane 32][8 halves]
__device__ __half g_wh[BATCH * 16 * 16 * 32 * 8];        // 4 MB
// fp16 copy of x
__device__ __half g_xh[(size_t)BATCH * CIN * HW];        // 52 MB

__device__ __forceinline__ unsigned smem_u32(const void* p) {
    unsigned a;
    asm("{ .reg .u64 t; cvta.to.shared.u64 t, %1; cvt.u32.u64 %0, t; }" : "=r"(a) : "l"(p));
    return a;
}
__device__ __forceinline__ void cp_async16(unsigned dst, const void* src) {
    asm volatile("cp.async.cg.shared.global [%0], [%1], 16;" :: "r"(dst), "l"(src) : "memory");
}
#define CP_COMMIT() asm volatile("cp.async.commit_group;" ::: "memory")
#define CP_WAIT2()  asm volatile("cp.async.wait_group 2;" ::: "memory")
#define CP_WAIT1()  asm volatile("cp.async.wait_group 1;" ::: "memory")
#define CP_WAIT0()  asm volatile("cp.async.wait_group 0;" ::: "memory")

__device__ __forceinline__ void lds128(unsigned* r, unsigned addr) {
    asm volatile("ld.shared.v4.b32 {%0,%1,%2,%3}, [%4];"
                 : "=r"(r[0]), "=r"(r[1]), "=r"(r[2]), "=r"(r[3]) : "r"(addr));
}
__device__ __forceinline__ void ldmx2t(unsigned& b0, unsigned& b1, unsigned addr) {
    asm volatile("ldmatrix.sync.aligned.m8n8.x2.trans.shared.b16 {%0,%1}, [%2];"
                 : "=r"(b0), "=r"(b1) : "r"(addr));
}
__device__ __forceinline__ void mma16(float4& d, const unsigned* a, unsigned b0, unsigned b1) {
    asm volatile(
        "mma.sync.aligned.m16n8k16.row.col.f32.f16.f16.f32 "
        "{%0,%1,%2,%3}, {%4,%5,%6,%7}, {%8,%9}, {%0,%1,%2,%3};"
        : "+f"(d.x), "+f"(d.y), "+f"(d.z), "+f"(d.w)
        : "r"(a[0]), "r"(a[1]), "r"(a[2]), "r"(a[3]), "r"(b0), "r"(b1));
}

// ---------------------------------------------------------------------------
// Kernel 1: global average pool + fp16 copy of x
// ---------------------------------------------------------------------------
__global__ void pool_kernel(const float* __restrict__ x) {
    const int bc = blockIdx.x;
    const float* __restrict__ p = x + (size_t)bc * HW;
    __half2* __restrict__ q2 = (__half2*)(g_xh + (size_t)bc * HW);
    const int tid = threadIdx.x;

    float s = 0.0f;
    const float4* p4 = (const float4*)p;
    for (int i = tid; i < HW / 4; i += 256) {
        float4 v = p4[i];
        s += v.x + v.y + v.z + v.w;
        __half2 h2[2];
        h2[0] = __floats2half2_rn(v.x, v.y);
        h2[1] = __floats2half2_rn(v.z, v.w);
        *(uint2*)(q2 + i * 2) = *(uint2*)h2;
    }
    for (int off = 16; off > 0; off >>= 1)
        s += __shfl_xor_sync(0xFFFFFFFFu, s, off);

    __shared__ float red[8];
    if ((tid & 31) == 0) red[tid >> 5] = s;
    __syncthreads();
    if (tid == 0) {
        float t = 0.0f;
        #pragma unroll
        for (int w = 0; w < 8; w++) t += red[w];
        g_pooled[bc] = t * (1.0f / (float)HW);
    }
}

// ---------------------------------------------------------------------------
// Kernel 2: MLP + softmax -> attn (256 threads, 4-way split dot)
// ---------------------------------------------------------------------------
__global__ void attn_kernel(const float* __restrict__ w1,
                            const float* __restrict__ b1,
                            const float* __restrict__ w2,
                            const float* __restrict__ b2) {
    const int b = blockIdx.x;
    const int t = threadIdx.x;                 // 256

    __shared__ float sp[CIN];
    __shared__ float sh[CHID];
    __shared__ float sl[NEXP];

    sp[t] = g_pooled[b * CIN + t];
    __syncthreads();

    {
        const int o = t >> 2, q = t & 3;
        float p = 0.0f;
        const float* w1r = w1 + o * CIN + q * 64;
        const float* spq = sp + q * 64;
        #pragma unroll 16
        for (int j = 0; j < 64; j++) p = fmaf(w1r[j], spq[j], p);
        p += __shfl_xor_sync(0xFFFFFFFFu, p, 1);
        p += __shfl_xor_sync(0xFFFFFFFFu, p, 2);
        if (q == 0) sh[o] = fmaxf(p + b1[o], 0.0f);
    }
    __syncthreads();

    if (t < NEXP) {
        float l = b2[t];
        const float* w2r = w2 + t * CHID;
        #pragma unroll
        for (int j = 0; j < CHID; j++) l = fmaf(w2r[j], sh[j], l);
        sl[t] = l;
    }
    __syncthreads();

    if (t == 0) {
        float m = sl[0];
        #pragma unroll
        for (int e = 1; e < NEXP; e++) m = fmaxf(m, sl[e]);
        float sum = 0.0f;
        float ex[NEXP];
        #pragma unroll
        for (int e = 0; e < NEXP; e++) { ex[e] = __expf(sl[e] - m); sum += ex[e]; }
        float inv = 1.0f / sum;
        #pragma unroll
        for (int e = 0; e < NEXP; e++) g_attn[b * NEXP + e] = ex[e] * inv;
    }
}

// ---------------------------------------------------------------------------
// Kernel 3: w_dyn = attn . weights -> fp16 fragment layout, coalesced STG.128.
// ---------------------------------------------------------------------------
__global__ __launch_bounds__(512)
void wdyn_kernel(const float* __restrict__ weights) {
    const int mt = blockIdx.x;
    const int b0 = blockIdx.y * 4;
    const int t  = threadIdx.x;
    const int kstep = t >> 5;
    const int lane  = t & 31;

    __shared__ float sa[BATCH][NEXP];
    if (t < BATCH * NEXP) ((float*)sa)[t] = g_attn[t];
    __syncthreads();

    float w[8][NEXP];
    #pragma unroll
    for (int hp = 0; hp < 4; hp++) {
        const int r8 = hp & 1;
        const int k8 = hp >> 1;
        const int co = mt * 16 + r8 * 8 + (lane >> 2);
        const int ci = kstep * 16 + k8 * 8 + (lane & 3) * 2;
        #pragma unroll
        for (int e = 0; e < NEXP; e++) {
            const float2 v = *(const float2*)(weights + ((size_t)e * COUT + co) * CIN + ci);
            w[2 * hp][e] = v.x;
            w[2 * hp + 1][e] = v.y;
        }
    }

    #pragma unroll
    for (int bb = 0; bb < 4; bb++) {
        const int b = b0 + bb;
        float av[NEXP];
        #pragma unroll
        for (int e = 0; e < NEXP; e++) av[e] = sa[b][e];
        __half2 h2[4];
        #pragma unroll
        for (int hp = 0; hp < 4; hp++) {
            float s0 = 0.0f, s1 = 0.0f;
            #pragma unroll
            for (int e = 0; e < NEXP; e++) {
                s0 = fmaf(av[e], w[2 * hp][e], s0);
                s1 = fmaf(av[e], w[2 * hp + 1][e], s1);
            }
            h2[hp] = __floats2half2_rn(s0, s1);
        }
        const size_t unit = (((size_t)b * 16 + mt) * 16 + kstep) * 32 + lane;
        *(uint4*)(g_wh + unit * 8) = *(uint4*)h2;
    }
}

// ---------------------------------------------------------------------------
// Kernel 4: fp16 m16n8k16 batched GEMM, PERSISTENT CTAs.
//   One wave of CTAs (4/SM); each walks ~6 tiles (64x112) via a flat chunk
//   stream; the 4-stage cp.async ring never drains across tile boundaries.
//   Tile order: n fastest (same A slice reused from L2 across 28 tiles).
// ---------------------------------------------------------------------------
__global__ __launch_bounds__(128, 4)
void gemm_mma(float* __restrict__ out) {
    extern __shared__ char smc[];
    const unsigned sbase = smem_u32(smc);

    const int tid  = threadIdx.x;
    const int wid  = tid >> 5;
    const int lane = tid & 31;
    const int wm = wid >> 1;          // 0..1  (m offset 32*wm)
    const int wn = wid & 1;           // 0..1  (n offset 56*wn)

    const int bid  = blockIdx.x;
    const int GRID = gridDim.x;
    const int ntiles  = (NTILES - bid + GRID - 1) / GRID;
    const int totalcc = ntiles * NCHPT;

    // B cp.async mapping: 448 16B units (32 rows x 14); 128 threads
    const int kr0 = tid / 14,  nc0 = tid % 14;
    const int kr1 = (tid + 128) / 14, nc1 = (tid + 128) % 14;
    const int kr2 = (tid + 256) / 14, nc2 = (tid + 256) % 14;
    const int kr3 = (tid + 384) / 14, nc3 = (tid + 384) % 14;   // tid < 64

    float4 acc[2][7];
    #pragma unroll
    for (int i = 0; i < 2; i++)
        #pragma unroll
        for (int j = 0; j < 7; j++)
            acc[i][j] = make_float4(0.f, 0.f, 0.f, 0.f);

    // issue chunk cc of this CTA's flat stream into stage cc%4
    auto issue = [&](int cc) {
        const int tt = cc >> 3, c = cc & 7;
        const int tile = bid + tt * GRID;
        const int nb = tile % 28;
        const int rest = tile / 28;
        const int mb = rest & 3;
        const int b  = rest >> 2;
        const __half* Afrag = g_wh + (size_t)(b * 16 + mb * 4) * (16 * 32 * 8);
        const __half* Bg = g_xh + (size_t)b * CIN * HW + nb * 112;

        const unsigned abase = sbase + (unsigned)((cc & 3) * STG_BYTES);
        const unsigned bbase = abase + A_BYTES;
        // A: 256 units; 2 per thread.  unit u: mt=u>>6, ks=(u>>5)&1, l=u&31
        #pragma unroll
        for (int i = 0; i < 2; i++) {
            const int u = tid * 2 + i;
            const int mt = u >> 6, ks = (u >> 5) & 1, l = u & 31;
            cp_async16(abase + (unsigned)u * 16,
                       Afrag + ((size_t)(mt * 16 + 2 * c + ks) * 32 + l) * 8);
        }
        const int k0 = c * BK;
        cp_async16(bbase + (unsigned)(kr0 * 240 + nc0 * 16),
                   Bg + (size_t)(k0 + kr0) * HW + nc0 * 8);
        cp_async16(bbase + (unsigned)(kr1 * 240 + nc1 * 16),
                   Bg + (size_t)(k0 + kr1) * HW + nc1 * 8);
        cp_async16(bbase + (unsigned)(kr2 * 240 + nc2 * 16),
                   Bg + (size_t)(k0 + kr2) * HW + nc2 * 8);
        if (tid < 64)
            cp_async16(bbase + (unsigned)(kr3 * 240 + nc3 * 16),
                       Bg + (size_t)(k0 + kr3) * HW + nc3 * 8);
    };

    // ---- prologue: 3 chunks in flight ----
    issue(0); CP_COMMIT();
    if (totalcc > 1) { issue(1); } CP_COMMIT();
    if (totalcc > 2) { issue(2); } CP_COMMIT();

    const unsigned bRow = (unsigned)((lane & 15) * 240 + wn * 112);
    const int rr = lane >> 2;
    const int t2 = (lane & 3) * 2;

    for (int cc = 0; cc < totalcc; cc++) {
        const int rem = totalcc - 1 - cc;
        if (rem >= 2) CP_WAIT2();
        else if (rem == 1) CP_WAIT1();
        else CP_WAIT0();
        __syncthreads();

        if (cc + 3 < totalcc) { issue(cc + 3); CP_COMMIT(); }

        const unsigned aS = sbase + (unsigned)((cc & 3) * STG_BYTES);
        const unsigned bS = aS + A_BYTES;

        #pragma unroll
        for (int ks = 0; ks < 2; ks++) {
            unsigned a0[4], a1[4];
            lds128(a0, aS + (unsigned)((((wm * 2 + 0) * 2 + ks) * 32 + lane) * 16));
            lds128(a1, aS + (unsigned)((((wm * 2 + 1) * 2 + ks) * 32 + lane) * 16));
            const unsigned bk = bS + (unsigned)(ks * 3840) + bRow;
            #pragma unroll
            for (int nt = 0; nt < 7; nt++) {
                unsigned b0, b1;
                ldmx2t(b0, b1, bk + (unsigned)(nt * 16));
                mma16(acc[0][nt], a0, b0, b1);
                mma16(acc[1][nt], a1, b0, b1);
            }
        }

        if ((cc & 7) == 7) {
            // ---- tile epilogue (register-only; overlaps in-flight loads) ----
            const int tile = bid + (cc >> 3) * GRID;
            const int nb = tile % 28;
            const int rest = tile / 28;
            const int mb = rest & 3;
            const int b  = rest >> 2;
            float* __restrict__ C = out + (size_t)b * COUT * HW
                                  + (size_t)(mb * BM + wm * 32) * HW + nb * 112 + wn * 56;
            #pragma unroll
            for (int it = 0; it < 2; it++)
                #pragma unroll
                for (int nt = 0; nt < 7; nt++) {
                    float* p0 = C + (size_t)(it * 16 + rr) * HW + nt * 8 + t2;
                    __stcs((float2*)p0, make_float2(acc[it][nt].x, acc[it][nt].y));
                    __stcs((float2*)(p0 + 8 * HW), make_float2(acc[it][nt].z, acc[it][nt].w));
                    acc[it][nt] = make_float4(0.f, 0.f, 0.f, 0.f);
                }
        }
    }
}

// ---------------------------------------------------------------------------
// Launch
// ---------------------------------------------------------------------------
extern "C" void kernel_launch(void* const* d_in, const int* in_sizes, int n_in,
                              void* d_out, int out_size) {
    const float* x       = (const float*)d_in[0];
    const float* weights = (const float*)d_in[1];
    const float* w1      = (const float*)d_in[2];
    const float* b1      = (const float*)d_in[3];
    const float* w2      = (const float*)d_in[4];
    const float* b2      = (const float*)d_in[5];
    float* out = (float*)d_out;

    pool_kernel<<<BATCH * CIN, 256>>>(x);
    attn_kernel<<<BATCH, 256>>>(w1, b1, w2, b2);
    wdyn_kernel<<<dim3(16, 8), 512>>>(weights);

    int sms = 148;
    cudaDeviceGetAttribute(&sms, cudaDevAttrMultiProcessorCount, 0);
    int grid = sms * 4;
    if (grid > NTILES) grid = NTILES;

    cudaFuncSetAttribute(gemm_mma, cudaFuncAttributeMaxDynamicSharedMemorySize, SM_BYTES);
    gemm_mma<<<grid, 128, SM_BYTES>>>(out);
}

// round 15
// speedup vs baseline: 1.2604x; 1.0908x over previous
#include <cuda_runtime.h>
#include <cuda_fp16.h>

// Problem constants
#define BATCH 32
#define CIN   256
#define COUT  256
#define NEXP  8
#define CHID  64
#define HW    3136   // 56*56

// GEMM tiling (R8 skeleton): CTA 128 x 112, 8 warps (4m x 2n), warp tile 32 x 56
#define BM 128
#define BK 32             // 2 k-steps of 16
#define NCHUNKS (CIN / BK)
#define NSTAGES 5

// per-stage smem bytes: A = 8 mt * 2 ks * 32 lane * 16B = 8192; B = 32 * 240 = 7680
#define A_BYTES 8192
#define STG_BYTES 15872
#define SM_BYTES (NSTAGES * STG_BYTES)   // 79360

// Device scratch (allocation-free per harness rules)
__device__ float g_pooled[BATCH * CIN];
__device__ float g_attn[BATCH * NEXP];
// A (w_dyn) fp16 in m16n8k16 A-fragment layout: [b][mt 16][kstep 16][lane 32][8 halves]
__device__ __half g_wh[BATCH * 16 * 16 * 32 * 8];        // 4 MB
// fp16 copy of x
__device__ __half g_xh[(size_t)BATCH * CIN * HW];        // 52 MB

__device__ __forceinline__ unsigned smem_u32(const void* p) {
    unsigned a;
    asm("{ .reg .u64 t; cvta.to.shared.u64 t, %1; cvt.u32.u64 %0, t; }" : "=r"(a) : "l"(p));
    return a;
}
__device__ __forceinline__ void cp_async16(unsigned dst, const void* src) {
    asm volatile("cp.async.cg.shared.global [%0], [%1], 16;" :: "r"(dst), "l"(src) : "memory");
}
#define CP_COMMIT() asm volatile("cp.async.commit_group;" ::: "memory")
#define CP_WAIT3()  asm volatile("cp.async.wait_group 3;" ::: "memory")
#define CP_WAIT2()  asm volatile("cp.async.wait_group 2;" ::: "memory")
#define CP_WAIT1()  asm volatile("cp.async.wait_group 1;" ::: "memory")
#define CP_WAIT0()  asm volatile("cp.async.wait_group 0;" ::: "memory")

__device__ __forceinline__ void lds128(unsigned* r, unsigned addr) {
    asm volatile("ld.shared.v4.b32 {%0,%1,%2,%3}, [%4];"
                 : "=r"(r[0]), "=r"(r[1]), "=r"(r[2]), "=r"(r[3]) : "r"(addr));
}
__device__ __forceinline__ void ldmx2t(unsigned& b0, unsigned& b1, unsigned addr) {
    asm volatile("ldmatrix.sync.aligned.m8n8.x2.trans.shared.b16 {%0,%1}, [%2];"
                 : "=r"(b0), "=r"(b1) : "r"(addr));
}
__device__ __forceinline__ void ldmx4t(unsigned& b0, unsigned& b1, unsigned& b2, unsigned& b3,
                                       unsigned addr) {
    asm volatile("ldmatrix.sync.aligned.m8n8.x4.trans.shared.b16 {%0,%1,%2,%3}, [%4];"
                 : "=r"(b0), "=r"(b1), "=r"(b2), "=r"(b3) : "r"(addr));
}
__device__ __forceinline__ void mma16(float4& d, const unsigned* a, unsigned b0, unsigned b1) {
    asm volatile(
        "mma.sync.aligned.m16n8k16.row.col.f32.f16.f16.f32 "
        "{%0,%1,%2,%3}, {%4,%5,%6,%7}, {%8,%9}, {%0,%1,%2,%3};"
        : "+f"(d.x), "+f"(d.y), "+f"(d.z), "+f"(d.w)
        : "r"(a[0]), "r"(a[1]), "r"(a[2]), "r"(a[3]), "r"(b0), "r"(b1));
}

// ---------------------------------------------------------------------------
// Kernel 1: global average pool + fp16 copy of x
// ---------------------------------------------------------------------------
__global__ void pool_kernel(const float* __restrict__ x) {
    const int bc = blockIdx.x;
    const float* __restrict__ p = x + (size_t)bc * HW;
    __half2* __restrict__ q2 = (__half2*)(g_xh + (size_t)bc * HW);
    const int tid = threadIdx.x;

    float s = 0.0f;
    const float4* p4 = (const float4*)p;
    for (int i = tid; i < HW / 4; i += 256) {
        float4 v = p4[i];
        s += v.x + v.y + v.z + v.w;
        __half2 h2[2];
        h2[0] = __floats2half2_rn(v.x, v.y);
        h2[1] = __floats2half2_rn(v.z, v.w);
        *(uint2*)(q2 + i * 2) = *(uint2*)h2;
    }
    for (int off = 16; off > 0; off >>= 1)
        s += __shfl_xor_sync(0xFFFFFFFFu, s, off);

    __shared__ float red[8];
    if ((tid & 31) == 0) red[tid >> 5] = s;
    __syncthreads();
    if (tid == 0) {
        float t = 0.0f;
        #pragma unroll
        for (int w = 0; w < 8; w++) t += red[w];
        g_pooled[bc] = t * (1.0f / (float)HW);
    }
}

// ---------------------------------------------------------------------------
// Kernel 2: MLP + softmax -> attn (256 threads, 4-way split dot)
// ---------------------------------------------------------------------------
__global__ void attn_kernel(const float* __restrict__ w1,
                            const float* __restrict__ b1,
                            const float* __restrict__ w2,
                            const float* __restrict__ b2) {
    const int b = blockIdx.x;
    const int t = threadIdx.x;                 // 256

    __shared__ float sp[CIN];
    __shared__ float sh[CHID];
    __shared__ float sl[NEXP];

    sp[t] = g_pooled[b * CIN + t];
    __syncthreads();

    {
        const int o = t >> 2, q = t & 3;
        float p = 0.0f;
        const float* w1r = w1 + o * CIN + q * 64;
        const float* spq = sp + q * 64;
        #pragma unroll 16
        for (int j = 0; j < 64; j++) p = fmaf(w1r[j], spq[j], p);
        p += __shfl_xor_sync(0xFFFFFFFFu, p, 1);
        p += __shfl_xor_sync(0xFFFFFFFFu, p, 2);
        if (q == 0) sh[o] = fmaxf(p + b1[o], 0.0f);
    }
    __syncthreads();

    if (t < NEXP) {
        float l = b2[t];
        const float* w2r = w2 + t * CHID;
        #pragma unroll
        for (int j = 0; j < CHID; j++) l = fmaf(w2r[j], sh[j], l);
        sl[t] = l;
    }
    __syncthreads();

    if (t == 0) {
        float m = sl[0];
        #pragma unroll
        for (int e = 1; e < NEXP; e++) m = fmaxf(m, sl[e]);
        float sum = 0.0f;
        float ex[NEXP];
        #pragma unroll
        for (int e = 0; e < NEXP; e++) { ex[e] = __expf(sl[e] - m); sum += ex[e]; }
        float inv = 1.0f / sum;
        #pragma unroll
        for (int e = 0; e < NEXP; e++) g_attn[b * NEXP + e] = ex[e] * inv;
    }
}

// ---------------------------------------------------------------------------
// Kernel 3: w_dyn = attn . weights -> fp16 fragment layout, coalesced STG.128.
// ---------------------------------------------------------------------------
__global__ __launch_bounds__(512)
void wdyn_kernel(const float* __restrict__ weights) {
    const int mt = blockIdx.x;
    const int b0 = blockIdx.y * 4;
    const int t  = threadIdx.x;
    const int kstep = t >> 5;
    const int lane  = t & 31;

    __shared__ float sa[BATCH][NEXP];
    if (t < BATCH * NEXP) ((float*)sa)[t] = g_attn[t];
    __syncthreads();

    float w[8][NEXP];
    #pragma unroll
    for (int hp = 0; hp < 4; hp++) {
        const int r8 = hp & 1;
        const int k8 = hp >> 1;
        const int co = mt * 16 + r8 * 8 + (lane >> 2);
        const int ci = kstep * 16 + k8 * 8 + (lane & 3) * 2;
        #pragma unroll
        for (int e = 0; e < NEXP; e++) {
            const float2 v = *(const float2*)(weights + ((size_t)e * COUT + co) * CIN + ci);
            w[2 * hp][e] = v.x;
            w[2 * hp + 1][e] = v.y;
        }
    }

    #pragma unroll
    for (int bb = 0; bb < 4; bb++) {
        const int b = b0 + bb;
        float av[NEXP];
        #pragma unroll
        for (int e = 0; e < NEXP; e++) av[e] = sa[b][e];
        __half2 h2[4];
        #pragma unroll
        for (int hp = 0; hp < 4; hp++) {
            float s0 = 0.0f, s1 = 0.0f;
            #pragma unroll
            for (int e = 0; e < NEXP; e++) {
                s0 = fmaf(av[e], w[2 * hp][e], s0);
                s1 = fmaf(av[e], w[2 * hp + 1][e], s1);
            }
            h2[hp] = __floats2half2_rn(s0, s1);
        }
        const size_t unit = (((size_t)b * 16 + mt) * 16 + kstep) * 32 + lane;
        *(uint4*)(g_wh + unit * 8) = *(uint4*)h2;
    }
}

// ---------------------------------------------------------------------------
// Kernel 4: fp16 m16n8k16 batched GEMM (R8 skeleton + ldmatrix.x4 + 5 stages)
//   out[b] (256 x 3136) = w_dyn[b] @ x[b]
//   CTA 128 x 112; 8 warps (4m x 2n); warp tile 32 x 56; 5-stage cp.async ring
//   with up to 4 chunk-groups in flight.
// ---------------------------------------------------------------------------
__global__ __launch_bounds__(256, 2)
void gemm_mma(float* __restrict__ out) {
    extern __shared__ char smc[];
    const unsigned sbase = smem_u32(smc);

    const int tid  = threadIdx.x;
    const int wid  = tid >> 5;
    const int lane = tid & 31;
    const int wm = wid >> 1;          // 0..3  (m offset 32*wm)
    const int wn = wid & 1;           // 0..1  (n offset 56*wn)

    const int n0 = blockIdx.x * 112;
    const int mb = blockIdx.y;        // 0..1
    const int b  = blockIdx.z;

    // A fragment source: mtiles mb*8 .. mb*8+7, 16 ksteps each
    const __half* __restrict__ Afrag = g_wh + (size_t)(b * 16 + mb * 8) * (16 * 32 * 8);
    const __half* __restrict__ Bg = g_xh + (size_t)b * CIN * HW;

    // B cp.async mapping: 448 16B units (32 rows x 14)
    const int kr0 = tid / 14, nc0 = tid % 14;
    const int kr1 = (tid + 256) / 14, nc1 = (tid + 256) % 14;   // tid < 192

    float4 acc[2][7];
    #pragma unroll
    for (int i = 0; i < 2; i++)
        #pragma unroll
        for (int j = 0; j < 7; j++)
            acc[i][j] = make_float4(0.f, 0.f, 0.f, 0.f);

    auto issue = [&](int c, int s) {
        const unsigned abase = sbase + (unsigned)(s * STG_BYTES);
        const unsigned bbase = abase + A_BYTES;
        // A: 512 units; 2 per thread.  unit u: mt=u>>6, ks=(u>>5)&1, l=u&31
        #pragma unroll
        for (int i = 0; i < 2; i++) {
            const int u = tid * 2 + i;
            const int mt = u >> 6, ks = (u >> 5) & 1, l = u & 31;
            cp_async16(abase + (unsigned)u * 16,
                       Afrag + ((size_t)(mt * 16 + 2 * c + ks) * 32 + l) * 8);
        }
        const int k0 = c * BK;
        cp_async16(bbase + (unsigned)(kr0 * 240 + nc0 * 16),
                   Bg + (size_t)(k0 + kr0) * HW + n0 + nc0 * 8);
        if (tid < 192)
            cp_async16(bbase + (unsigned)(kr1 * 240 + nc1 * 16),
                       Bg + (size_t)(k0 + kr1) * HW + n0 + nc1 * 8);
    };

    // ---- prologue: 4 stages in flight ----
    issue(0, 0); CP_COMMIT();
    issue(1, 1); CP_COMMIT();
    issue(2, 2); CP_COMMIT();
    issue(3, 3); CP_COMMIT();

    // ldmatrix addressing:
    //  x4: lanes 0-15 -> k rows 0-15 at col n, lanes 16-31 -> same rows at col n+8
    const unsigned bRow4 = (unsigned)((lane & 15) * 240 + wn * 112 + (lane >> 4) * 16);
    const unsigned bRow2 = (unsigned)((lane & 15) * 240 + wn * 112);

    for (int c = 0; c < NCHUNKS; c++) {
        const int allowed = (7 - c < 3) ? (7 - c) : 3;
        if (allowed == 3) CP_WAIT3();
        else if (allowed == 2) CP_WAIT2();
        else if (allowed == 1) CP_WAIT1();
        else CP_WAIT0();
        __syncthreads();

        if (c + 4 < NCHUNKS) { issue(c + 4, (c + 4) % NSTAGES); CP_COMMIT(); }

        const unsigned aS = sbase + (unsigned)((c % NSTAGES) * STG_BYTES);
        const unsigned bS = aS + A_BYTES;

        #pragma unroll
        for (int ks = 0; ks < 2; ks++) {
            unsigned a0[4], a1[4];
            lds128(a0, aS + (unsigned)((((wm * 2 + 0) * 2 + ks) * 32 + lane) * 16));
            lds128(a1, aS + (unsigned)((((wm * 2 + 1) * 2 + ks) * 32 + lane) * 16));
            const unsigned bk = bS + (unsigned)(ks * 3840);
            #pragma unroll
            for (int p = 0; p < 3; p++) {
                unsigned b0, b1, b2, b3;
                ldmx4t(b0, b1, b2, b3, bk + bRow4 + (unsigned)(p * 32));
                mma16(acc[0][2 * p],     a0, b0, b1);
                mma16(acc[1][2 * p],     a1, b0, b1);
                mma16(acc[0][2 * p + 1], a0, b2, b3);
                mma16(acc[1][2 * p + 1], a1, b2, b3);
            }
            {
                unsigned b0, b1;
                ldmx2t(b0, b1, bk + bRow2 + 96u);
                mma16(acc[0][6], a0, b0, b1);
                mma16(acc[1][6], a1, b0, b1);
            }
        }
    }

    // ---- epilogue ----
    const int rr = lane >> 2;
    const int t2 = (lane & 3) * 2;
    float* __restrict__ C = out + (size_t)b * COUT * HW
                          + (size_t)(mb * BM + wm * 32) * HW + n0 + wn * 56;
    #pragma unroll
    for (int it = 0; it < 2; it++)
        #pragma unroll
        for (int nt = 0; nt < 7; nt++) {
            float* p0 = C + (size_t)(it * 16 + rr) * HW + nt * 8 + t2;
            __stcs((float2*)p0, make_float2(acc[it][nt].x, acc[it][nt].y));
            __stcs((float2*)(p0 + 8 * HW), make_float2(acc[it][nt].z, acc[it][nt].w));
        }
}

// ---------------------------------------------------------------------------
// Launch
// ---------------------------------------------------------------------------
extern "C" void kernel_launch(void* const* d_in, const int* in_sizes, int n_in,
                              void* d_out, int out_size) {
    const float* x       = (const float*)d_in[0];
    const float* weights = (const float*)d_in[1];
    const float* w1      = (const float*)d_in[2];
    const float* b1      = (const float*)d_in[3];
    const float* w2      = (const float*)d_in[4];
    const float* b2      = (const float*)d_in[5];
    float* out = (float*)d_out;

    pool_kernel<<<BATCH * CIN, 256>>>(x);
    attn_kernel<<<BATCH, 256>>>(w1, b1, w2, b2);
    wdyn_kernel<<<dim3(16, 8), 512>>>(weights);

    cudaFuncSetAttribute(gemm_mma, cudaFuncAttributeMaxDynamicSharedMemorySize, SM_BYTES);
    dim3 grid(HW / 112, COUT / BM, BATCH);   // 28 x 2 x 32
    gemm_mma<<<grid, 256, SM_BYTES>>>(out);
}